// round 5
// baseline (speedup 1.0000x reference)
#include <cuda_runtime.h>
#include <cuda_bf16.h>
#include <math_constants.h>

#define W      384
#define H      384
#define WV     96     // W / 4 float4 lanes per row
#define RPT    16     // rows per thread strip
#define STRIPS (H / RPT)          // 24
#define STRIPS_PER_BLK 4
// sigmoid(x) > 0.05  <=>  x > ln(0.05/0.95)
#define THRESH_X (-2.9444389791664403f)

__device__ __forceinline__ float4 neg_inf4() {
    float ni = -CUDART_INF_F;
    return make_float4(ni, ni, ni, ni);
}

// Load one row segment (float4 + left/right halo scalars), return the
// horizontal 3-max per lane; raw center values returned via *val_out.
__device__ __forceinline__ float4 load_hmax(const float* __restrict__ rowbase,
                                            int t, float4* val_out) {
    float4 v = *reinterpret_cast<const float4*>(rowbase + 4 * t);
    float left  = (t > 0)      ? __ldg(rowbase + 4 * t - 1) : -CUDART_INF_F;
    float right = (t < WV - 1) ? __ldg(rowbase + 4 * t + 4) : -CUDART_INF_F;
    *val_out = v;
    float4 h;
    h.x = fmaxf(left, fmaxf(v.x, v.y));
    h.y = fmaxf(v.x,  fmaxf(v.y, v.z));
    h.z = fmaxf(v.y,  fmaxf(v.z, v.w));
    h.w = fmaxf(v.z,  fmaxf(v.w, right));
    return h;
}

__device__ __forceinline__ float sigmoidf_fast(float x) {
    return 1.0f / (1.0f + __expf(-x));
}

__device__ __forceinline__ float peak_out(float v, float hp, float hc, float hn) {
    float m = fmaxf(hp, fmaxf(hc, hn));     // 3x3 max; hc already includes v
    return (v == m && v > THRESH_X) ? sigmoidf_fast(v) : 0.0f;
}

__global__ __launch_bounds__(WV * STRIPS_PER_BLK)
void heatmap_peaks_kernel(const float* __restrict__ in, float* __restrict__ out) {
    const int t     = threadIdx.x;                                  // 0..95
    const int strip = blockIdx.x * STRIPS_PER_BLK + threadIdx.y;    // 0..23
    const int p     = blockIdx.y;                                   // plane 0..271

    const float* plane  = in  + (size_t)p * (W * H);
    float*       oplane = out + (size_t)p * (W * H);
    const int r0 = strip * RPT;

    float4 hprev, hcur, hnext, vcur, vnext, vtmp;

    if (r0 > 0) hprev = load_hmax(plane + (size_t)(r0 - 1) * W, t, &vtmp);
    else        hprev = neg_inf4();
    hcur = load_hmax(plane + (size_t)r0 * W, t, &vcur);

    #pragma unroll 4
    for (int r = r0; r < r0 + RPT; ++r) {
        if (r + 1 < H) {
            hnext = load_hmax(plane + (size_t)(r + 1) * W, t, &vnext);
        } else {
            hnext = neg_inf4();
            vnext = neg_inf4();
        }

        float4 o;
        o.x = peak_out(vcur.x, hprev.x, hcur.x, hnext.x);
        o.y = peak_out(vcur.y, hprev.y, hcur.y, hnext.y);
        o.z = peak_out(vcur.z, hprev.z, hcur.z, hnext.z);
        o.w = peak_out(vcur.w, hprev.w, hcur.w, hnext.w);

        *reinterpret_cast<float4*>(oplane + (size_t)r * W + 4 * t) = o;

        hprev = hcur;
        hcur  = hnext;
        vcur  = vnext;
    }
}

extern "C" void kernel_launch(void* const* d_in, const int* in_sizes, int n_in,
                              void* d_out, int out_size) {
    (void)in_sizes; (void)n_in; (void)out_size;
    const float* in = (const float*)d_in[0];
    float* out = (float*)d_out;

    dim3 block(WV, STRIPS_PER_BLK);                 // 96 x 4 = 384 threads
    dim3 grid(STRIPS / STRIPS_PER_BLK, 16 * 17);    // (6, 272)
    heatmap_peaks_kernel<<<grid, block>>>(in, out);
}

// round 6
// speedup vs baseline: 1.3931x; 1.3931x over previous
#include <cuda_runtime.h>
#include <cuda_bf16.h>
#include <math_constants.h>

#define W      384
#define H      384
#define WV     96     // W / 4 float4 lanes per row
#define RPT    16     // rows per thread strip
#define STRIPS (H / RPT)          // 24
#define SPB    4                  // strips per block
// sigmoid(x) > 0.05  <=>  x > ln(0.05/0.95)
#define THRESH_X (-2.9444389791664403f)

struct RowLd { float4 v; float lo; float hi; };

__device__ __forceinline__ RowLd load_row(const float* __restrict__ plane,
                                          int q, int t) {
    RowLd r;
    if ((unsigned)q < (unsigned)H) {
        const float* rowbase = plane + (size_t)q * W;
        r.v  = *reinterpret_cast<const float4*>(rowbase + 4 * t);
        r.lo = (t > 0)      ? __ldg(rowbase + 4 * t - 1) : -CUDART_INF_F;
        r.hi = (t < WV - 1) ? __ldg(rowbase + 4 * t + 4) : -CUDART_INF_F;
    } else {
        r.v  = make_float4(-CUDART_INF_F, -CUDART_INF_F,
                           -CUDART_INF_F, -CUDART_INF_F);
        r.lo = -CUDART_INF_F;
        r.hi = -CUDART_INF_F;
    }
    return r;
}

__device__ __forceinline__ float4 hmax(const RowLd& a) {
    float4 h;
    h.x = fmaxf(a.lo,  fmaxf(a.v.x, a.v.y));
    h.y = fmaxf(a.v.x, fmaxf(a.v.y, a.v.z));
    h.z = fmaxf(a.v.y, fmaxf(a.v.z, a.v.w));
    h.w = fmaxf(a.v.z, fmaxf(a.v.w, a.hi));
    return h;
}

__device__ __forceinline__ float sigmoidf_fast(float x) {
    return 1.0f / (1.0f + __expf(-x));
}

__device__ __forceinline__ float peak_out(float v, float hp, float hc, float hn) {
    float m = fmaxf(hp, fmaxf(hc, hn));     // 3x3 max; hc already includes v
    return (v == m && v > THRESH_X) ? sigmoidf_fast(v) : 0.0f;
}

__global__ __launch_bounds__(WV * SPB, 4)
void heatmap_peaks_kernel(const float* __restrict__ in, float* __restrict__ out) {
    const int t     = threadIdx.x;                           // 0..95
    const int strip = blockIdx.x * SPB + threadIdx.y;        // 0..23
    const int p     = blockIdx.y;                            // plane 0..271

    const float* plane  = in  + (size_t)p * (W * H);
    float*       oplane = out + (size_t)p * (W * H);
    const int r0 = strip * RPT;

    // Prologue: rows r0-1, r0, r0+1 issued back-to-back (independent).
    RowLd A = load_row(plane, r0 - 1, t);
    RowLd B = load_row(plane, r0,     t);
    RowLd C = load_row(plane, r0 + 1, t);   // stays raw; consumed next iter

    float4 hprev = hmax(A);
    float4 hcur  = hmax(B);
    float4 vcur  = B.v;

    float* orow = oplane + (size_t)r0 * W + 4 * t;

    #pragma unroll
    for (int i = 0; i < RPT; ++i) {
        // Prefetch row r+2 FIRST — its latency overlaps this iteration's
        // compute and the consume of C happens a full iteration after issue.
        RowLd D = load_row(plane, r0 + i + 2, t);

        float4 hnext = hmax(C);
        float4 vnext = C.v;

        float4 o;
        o.x = peak_out(vcur.x, hprev.x, hcur.x, hnext.x);
        o.y = peak_out(vcur.y, hprev.y, hcur.y, hnext.y);
        o.z = peak_out(vcur.z, hprev.z, hcur.z, hnext.z);
        o.w = peak_out(vcur.w, hprev.w, hcur.w, hnext.w);

        __stcs(reinterpret_cast<float4*>(orow), o);   // streaming store
        orow += W;

        hprev = hcur;
        hcur  = hnext;
        vcur  = vnext;
        C     = D;
    }
}

extern "C" void kernel_launch(void* const* d_in, const int* in_sizes, int n_in,
                              void* d_out, int out_size) {
    (void)in_sizes; (void)n_in; (void)out_size;
    const float* in = (const float*)d_in[0];
    float* out = (float*)d_out;

    dim3 block(WV, SPB);                      // 96 x 4 = 384 threads
    dim3 grid(STRIPS / SPB, 16 * 17);         // (6, 272) = 1632 CTAs
    heatmap_peaks_kernel<<<grid, block>>>(in, out);
}